// round 4
// baseline (speedup 1.0000x reference)
#include <cuda_runtime.h>
#include <math.h>
#include <stdint.h>

// Problem constants (fixed by reference)
#define DIMN   2048
#define TSTEPS 256
#define KTOP   8
#define NPAIR  28
#define MSLOT  16
#define NTHR   512
#define EPT    4      // elements per thread: 512*4 = 2048

// Upper-triangle pair tables, row-major (matches np.triu_indices(8, k=1))
__constant__ int c_iu[NPAIR] = {0,0,0,0,0,0,0,1,1,1,1,1,1,2,2,2,2,2,3,3,3,3,4,4,4,5,5,6};
__constant__ int c_ju[NPAIR] = {1,2,3,4,5,6,7,2,3,4,5,6,7,3,4,5,6,7,4,5,6,7,5,6,7,6,7,7};

__device__ __forceinline__ void warp_argmax(float& v, int& ix) {
    // all-lanes butterfly argmax; ties -> lower index (matches lax.top_k)
#pragma unroll
    for (int off = 16; off; off >>= 1) {
        float ov = __shfl_xor_sync(0xffffffffu, v, off);
        int   oi = __shfl_xor_sync(0xffffffffu, ix, off);
        if (ov > v || (ov == v && oi < ix)) { v = ov; ix = oi; }
    }
}

__global__ __launch_bounds__(NTHR, 1)
void me_bind_kernel(const float* __restrict__ x,
                    const float* __restrict__ tape_re,
                    const float* __restrict__ tape_im,
                    const float* __restrict__ eta_p,
                    const float* __restrict__ tb_re_g,
                    const float* __restrict__ tb_im_g,
                    float* __restrict__ out)
{
    __shared__ float s_re[DIMN], s_im[DIMN];   // state mirror for warp0 gathers
    __shared__ float sh_h[DIMN];               // current h row
    __shared__ float d_re[DIMN], d_im[DIMN];   // scatter delta (read-then-zero)
    __shared__ float wv[128];                  // stage1 top-8 values (16 warps * 8)
    __shared__ int   wi[128];
    __shared__ int   top_idx[KTOP];
    __shared__ float red[17];

    const int tid  = threadIdx.x;
    const int lane = tid & 31;
    const int wid  = tid >> 5;
    const int b    = blockIdx.x;
    const float eta = fabsf(eta_p[0]);

    // transient table: warp0 lanes 0..15, one slot per lane, lives in registers
    int   t_ti = 0, t_tj = 0, t_cnt = 0;
    float t_mre = 0.f, t_mim = 0.f;

    // thread-local state + per-element constants
    float sre[EPT], sim[EPT], tbr[EPT], tbi[EPT];

    // ---- init: s0 = renorm(tape_re + i*tape_im) ----
    float psum = 0.f;
#pragma unroll
    for (int k = 0; k < EPT; k++) {
        int e = tid + k * NTHR;
        float a = tape_re[e], c = tape_im[e];
        sre[k] = a; sim[k] = c;
        psum += a * a + c * c;
        tbr[k] = tb_re_g[e]; tbi[k] = tb_im_g[e];
        d_re[e] = 0.f; d_im[e] = 0.f;
    }
    {
#pragma unroll
        for (int off = 16; off; off >>= 1) psum += __shfl_xor_sync(0xffffffffu, psum, off);
        if (lane == 0) red[wid] = psum;
        __syncthreads();
        if (tid < 16) {
            float v = red[tid];
#pragma unroll
            for (int off = 8; off; off >>= 1) v += __shfl_xor_sync(0xffffu, v, off);
            if (tid == 0) red[16] = v;
        }
        __syncthreads();
        float inv = 1.f / fmaxf(sqrtf(red[16]), 1e-8f);
#pragma unroll
        for (int k = 0; k < EPT; k++) {
            int e = tid + k * NTHR;
            sre[k] *= inv; sim[k] *= inv;
            s_re[e] = sre[k]; s_im[e] = sim[k];
        }
    }
    __syncthreads();

    const float* xb = x + (size_t)b * TSTEPS * DIMN;
    float*       ob = out + (size_t)b * TSTEPS * DIMN;

    for (int t = 0; t < TSTEPS; t++) {
        const float* hp = xb + (size_t)t * DIMN;

        // ---- phase 0: load h, c = h*s, |c|^2 ----
        float hv[EPT], m2[EPT];
#pragma unroll
        for (int k = 0; k < EPT; k++) {
            int e = tid + k * NTHR;
            float h = hp[e];
            hv[k] = h; sh_h[e] = h;
            float cr = h * sre[k], ci_ = h * sim[k];
            m2[k] = cr * cr + ci_ * ci_;
        }
        // prefetch next h row into L2
        if (t + 1 < TSTEPS) {
            const float* hn = hp + DIMN;
#pragma unroll
            for (int k = 0; k < EPT; k++)
                asm volatile("prefetch.global.L2 [%0];" :: "l"(hn + tid + k * NTHR));
        }

        // ---- stage 1: per-warp top-8 of 128 elements ----
        unsigned selm = 0;
        for (int r = 0; r < KTOP; r++) {
            float bv = -INFINITY; int bi = 0x7fffffff;
#pragma unroll
            for (int k = 0; k < EPT; k++)
                if (!((selm >> k) & 1u) && m2[k] > bv) { bv = m2[k]; bi = tid + k * NTHR; }
            float v = bv; int ix = bi;
            warp_argmax(v, ix);
#pragma unroll
            for (int k = 0; k < EPT; k++)
                if (tid + k * NTHR == ix) selm |= 1u << k;
            if (lane == 0) { wv[wid * KTOP + r] = v; wi[wid * KTOP + r] = ix; }
        }
        __syncthreads();   // (A)

        // ---- warp0 serial section ----
        if (wid == 0) {
            // stage 2: merge 128 candidates -> global top-8
            float cv[4]; int cix[4];
#pragma unroll
            for (int k = 0; k < 4; k++) { cv[k] = wv[lane * 4 + k]; cix[k] = wi[lane * 4 + k]; }
            unsigned sel2 = 0;
            for (int r = 0; r < KTOP; r++) {
                float bv = -INFINITY; int bi = 0x7fffffff;
#pragma unroll
                for (int k = 0; k < 4; k++)
                    if (!((sel2 >> k) & 1u) &&
                        (cv[k] > bv || (cv[k] == bv && cix[k] < bi))) { bv = cv[k]; bi = cix[k]; }
                float v = bv; int ix = bi;
                warp_argmax(v, ix);
#pragma unroll
                for (int k = 0; k < 4; k++)
                    if (cix[k] == ix) sel2 |= 1u << k;
                if (lane == 0) top_idx[r] = ix;
            }
            __syncwarp();

            // pair phase: score = Re(c_i * conj(c_j)) = tm_i*tm_j*cos(ph_i-ph_j)
            int ci = 0, cj = 0;
            float score = -INFINITY; bool pos = false;
            float sir = 0.f, sii = 0.f, sjr = 0.f, sji = 0.f;
            if (lane < NPAIR) {
                ci = top_idx[c_iu[lane]];
                cj = top_idx[c_ju[lane]];
                float hi_ = sh_h[ci], hj_ = sh_h[cj];
                sir = s_re[ci]; sii = s_im[ci];
                sjr = s_re[cj]; sji = s_im[cj];
                float cir = hi_ * sir, cii = hi_ * sii;
                float cjr = hj_ * sjr, cji = hj_ * sji;
                score = cir * cjr + cii * cji;
                pos = score > 0.f;
            }
            unsigned posb = __ballot_sync(0xffffffffu, pos);
            int n_pos = __popc(posb);
            unsigned bound = 0u;
            float pmre = 0.f, pmim = 0.f;
            if (n_pos > 0) {
                int n_bind = max(1, (int)((float)n_pos * 0.15f));     // f32 trunc, as jnp
                int theta_idx = min(n_bind - 1, n_pos - 1);
                float cur = pos ? score : -INFINITY;
                float theta = -INFINITY;
                for (int r = 0;; r++) {
                    float mv = cur; int ml = lane;
                    warp_argmax(mv, ml);
                    if (r == theta_idx) { theta = mv; break; }
                    if (lane == ml) cur = -INFINITY;                  // knock out one instance
                }
                bound = __ballot_sync(0xffffffffu, (lane < NPAIR) && (score >= theta));
            }
            if (lane < NPAIR) {
                // mnew = BETA * (s_ci * s_cj) / |s_ci * s_cj|
                float pr = sir * sjr - sii * sji;
                float pi = sir * sji + sii * sjr;
                float mag = sqrtf(pr * pr + pi * pi);
                float sc = 0.05f / fmaxf(mag, 1e-8f);
                pmre = pr * sc; pmim = pi * sc;
            }

            // sequential transient scan — only bound pairs mutate state
            unsigned bm = bound;
            while (bm) {
                int p = __ffs(bm) - 1; bm &= bm - 1;
                int   bci = __shfl_sync(0xffffffffu, ci,   p);
                int   bcj = __shfl_sync(0xffffffffu, cj,   p);
                float bmr = __shfl_sync(0xffffffffu, pmre, p);
                float bmi = __shfl_sync(0xffffffffu, pmim, p);
                bool act = (lane < MSLOT) && (t_cnt > 0);
                bool mat = act && ((t_ti == bci && t_tj == bcj) || (t_ti == bcj && t_tj == bci));
                unsigned mb = __ballot_sync(0xffffffffu, mat);
                if (mb) {
                    if (lane == __ffs(mb) - 1) t_cnt = 5;             // refresh
                } else {
                    unsigned fb = __ballot_sync(0xffffffffu, (lane < MSLOT) && t_cnt <= 0);
                    if (fb && lane == __ffs(fb) - 1) {                // insert at first free
                        t_ti = bci; t_tj = bcj; t_mre = bmr; t_mim = bmi; t_cnt = 5;
                    }
                }
            }

            // decay + liveness + scatter into delta
            if (lane < MSLOT) {
                t_mre *= 0.9f; t_mim *= 0.9f; t_cnt -= 1;
                bool alive = (t_cnt > 0) &&
                             (sqrtf(t_mre * t_mre + t_mim * t_mim) > 1e-6f);
                if (!alive) { t_cnt = 0; t_mre = 0.f; t_mim = 0.f; }
                else {
                    float ar = 0.1f * t_mre, ai = 0.1f * t_mim;
                    atomicAdd(&d_re[t_ti], ar); atomicAdd(&d_im[t_ti], ai);
                    atomicAdd(&d_re[t_tj], ar); atomicAdd(&d_im[t_tj], ai);
                }
            }
        }
        __syncthreads();   // (B)

        // ---- element update + renorm ----
        float nre[EPT], nim[EPT], em2[EPT];
        float ps = 0.f;
#pragma unroll
        for (int k = 0; k < EPT; k++) {
            int e = tid + k * NTHR;
            float ar = sre[k] + d_re[e];
            float ai = sim[k] + d_im[e];
            d_re[e] = 0.f; d_im[e] = 0.f;                  // fused clear for next step
            float rc = hv[k] * ar, ic = hv[k] * ai;
            float aic = fabsf(ic);
            bool res = (rc >  1e-6f) && (aic <  rc);
            bool tor = (rc < -1e-6f) || (aic >= fabsf(rc));
            float kf = (res || tor) ? 1.f : 0.f;           // res & tor are exclusive
            float tf = tor ? 1.f : 0.f;
            float ur = eta * (rc * kf + tf * tbr[k]);
            float ui = eta * (ic * kf + tf * tbi[k]);
            float a = sre[k] + ur, c2 = sim[k] + ui;       // note: original s, not s_aug
            nre[k] = a; nim[k] = c2;
            em2[k] = a * a + c2 * c2;
            ps += em2[k];
        }
        // block reduce norm^2
#pragma unroll
        for (int off = 16; off; off >>= 1) ps += __shfl_xor_sync(0xffffffffu, ps, off);
        if (lane == 0) red[wid] = ps;
        __syncthreads();   // (C)
        if (tid < 16) {
            float v = red[tid];
#pragma unroll
            for (int off = 8; off; off >>= 1) v += __shfl_xor_sync(0xffffu, v, off);
            if (tid == 0) red[16] = v;
        }
        __syncthreads();   // (D)
        float invn = 1.f / fmaxf(sqrtf(red[16]), 1e-8f);
#pragma unroll
        for (int k = 0; k < EPT; k++) {
            int e = tid + k * NTHR;
            float a = nre[k] * invn, c2 = nim[k] * invn;
            sre[k] = a; sim[k] = c2;
            s_re[e] = a; s_im[e] = c2;
            ob[(size_t)t * DIMN + e] = sqrtf(em2[k]) * invn;   // |s_new|
        }
    }
}

extern "C" void kernel_launch(void* const* d_in, const int* in_sizes, int n_in,
                              void* d_out, int out_size) {
    const float* x       = (const float*)d_in[0];
    const float* tape_re = (const float*)d_in[1];
    const float* tape_im = (const float*)d_in[2];
    const float* eta_p   = (const float*)d_in[3];
    const float* tb_re   = (const float*)d_in[4];
    const float* tb_im   = (const float*)d_in[5];
    float* out = (float*)d_out;

    int B = in_sizes[0] / (TSTEPS * DIMN);   // 64
    me_bind_kernel<<<B, NTHR>>>(x, tape_re, tape_im, eta_p, tb_re, tb_im, out);
}

// round 5
// speedup vs baseline: 1.3728x; 1.3728x over previous
#include <cuda_runtime.h>
#include <math.h>
#include <stdint.h>

// Problem constants (fixed by reference)
#define DIMN   2048
#define TSTEPS 256
#define KTOP   8
#define NPAIR  28
#define MSLOT  16
#define NTHR   512
#define EPT    4      // elements per thread: 512*4 = 2048
#define NW     16     // warps per block
#define CAP    256    // candidate buffer capacity
#define FULLM  0xffffffffu

// Upper-triangle pair tables, row-major (matches np.triu_indices(8, k=1))
__constant__ int c_iu[NPAIR] = {0,0,0,0,0,0,0,1,1,1,1,1,1,2,2,2,2,2,3,3,3,3,4,4,4,5,5,6};
__constant__ int c_ju[NPAIR] = {1,2,3,4,5,6,7,2,3,4,5,6,7,3,4,5,6,7,4,5,6,7,5,6,7,6,7,7};

__device__ __forceinline__ void warp_argmax(float& v, int& ix) {
    // all-lanes butterfly argmax; ties -> lower index (matches lax.top_k)
#pragma unroll
    for (int off = 16; off; off >>= 1) {
        float ov = __shfl_xor_sync(FULLM, v, off);
        int   oi = __shfl_xor_sync(FULLM, ix, off);
        if (ov > v || (ov == v && oi < ix)) { v = ov; ix = oi; }
    }
}

// Shared update formula so warp0's correction path and the owners' zero-delta
// path produce bit-identical results for the same inputs.
__device__ __forceinline__ void upd_elem(float sr, float si, float dr, float di,
                                         float h, float tr, float tii, float eta,
                                         float& a, float& c) {
    float rc = h * (sr + dr), ic = h * (si + di);
    float aic = fabsf(ic);
    bool res = (rc >  1e-6f) && (aic <  rc);
    bool tor = (rc < -1e-6f) || (aic >= fabsf(rc));
    float kf = (res || tor) ? 1.f : 0.f;   // res & tor mutually exclusive
    float tf = tor ? 1.f : 0.f;
    a = sr + eta * (rc * kf + tf * tr);
    c = si + eta * (ic * kf + tf * tii);
}

__global__ __launch_bounds__(NTHR, 1)
void me_bind_kernel(const float* __restrict__ x,
                    const float* __restrict__ tape_re,
                    const float* __restrict__ tape_im,
                    const float* __restrict__ eta_p,
                    const float* __restrict__ tb_re_g,
                    const float* __restrict__ tb_im_g,
                    float* __restrict__ out)
{
    __shared__ float s_re[DIMN], s_im[DIMN];    // state mirror for warp0 gathers
    __shared__ float sh_h[DIMN];                // current h row
    __shared__ float d_re[DIMN], d_im[DIMN];    // sparse delta / corrected values
    __shared__ float wmax[NW];                  // per-warp max of m2
    __shared__ int   cand_idx[CAP];
    __shared__ float cand_val[CAP];
    __shared__ int   cand_cnt;
    __shared__ int   top_idx[KTOP];
    __shared__ float red[NW + 1];               // 16 warp partials + correction
    __shared__ unsigned bmap[DIMN / 32];        // affected-element bitmap

    const int tid  = threadIdx.x;
    const int lane = tid & 31;
    const int wid  = tid >> 5;
    const int b    = blockIdx.x;
    const float eta = fabsf(eta_p[0]);

    // transient table: warp0 lanes 0..15, one slot per lane, in registers
    int   t_ti = 0, t_tj = 0, t_cnt = 0;
    float t_mre = 0.f, t_mim = 0.f;

    float sre[EPT], sim[EPT], tbr[EPT], tbi[EPT];

    // ---- init: s0 = renorm(tape_re + i*tape_im) ----
    float psum = 0.f;
#pragma unroll
    for (int k = 0; k < EPT; k++) {
        int e = tid + k * NTHR;
        float a = tape_re[e], c = tape_im[e];
        sre[k] = a; sim[k] = c;
        psum += a * a + c * c;
        tbr[k] = tb_re_g[e]; tbi[k] = tb_im_g[e];
        d_re[e] = 0.f; d_im[e] = 0.f;
    }
    if (tid < DIMN / 32) bmap[tid] = 0u;
    {
#pragma unroll
        for (int off = 16; off; off >>= 1) psum += __shfl_xor_sync(FULLM, psum, off);
        if (lane == 0) red[wid] = psum;
        __syncthreads();
        if (tid < NW) {
            float v = red[tid];
#pragma unroll
            for (int off = 8; off; off >>= 1) v += __shfl_xor_sync(0xffffu, v, off);
            if (tid == 0) red[NW] = v;
        }
        __syncthreads();
        float inv = 1.f / fmaxf(sqrtf(red[NW]), 1e-8f);
#pragma unroll
        for (int k = 0; k < EPT; k++) {
            int e = tid + k * NTHR;
            sre[k] *= inv; sim[k] *= inv;
            s_re[e] = sre[k]; s_im[e] = sim[k];
        }
    }
    __syncthreads();

    const float* xb = x + (size_t)b * TSTEPS * DIMN;
    float*       ob = out + (size_t)b * TSTEPS * DIMN;

    for (int t = 0; t < TSTEPS; t++) {
        const float* hp = xb + (size_t)t * DIMN;

        // ================= P1: load h, m2, per-warp max =================
        float hv[EPT], m2[EPT];
        float wmx = -INFINITY;
#pragma unroll
        for (int k = 0; k < EPT; k++) {
            int e = tid + k * NTHR;
            float h = hp[e];
            hv[k] = h; sh_h[e] = h;
            float cr = h * sre[k], ci_ = h * sim[k];
            m2[k] = cr * cr + ci_ * ci_;
            wmx = fmaxf(wmx, m2[k]);
        }
        if (t + 1 < TSTEPS) {
            const float* hn = hp + DIMN;
#pragma unroll
            for (int k = 0; k < EPT; k++)
                asm volatile("prefetch.global.L2 [%0];" :: "l"(hn + tid + k * NTHR));
        }
#pragma unroll
        for (int off = 16; off; off >>= 1)
            wmx = fmaxf(wmx, __shfl_xor_sync(FULLM, wmx, off));
        if (lane == 0) wmax[wid] = wmx;
        if (tid == 0) cand_cnt = 0;
        __syncthreads();   // (A)

        // ================= P2: theta (redundant per warp) + compaction =====
        float theta_sel;
        {
            float v = (lane < NW) ? wmax[lane] : -INFINITY;
            int rk = 0;
#pragma unroll
            for (int j = 0; j < NW; j++) {
                float vj = __shfl_sync(FULLM, v, j);
                if (vj > v || (vj == v && j < lane)) rk++;
            }
            unsigned b8 = __ballot_sync(FULLM, (lane < NW) && (rk == KTOP - 1));
            theta_sel = __shfl_sync(FULLM, v, __ffs(b8) - 1);
        }
#pragma unroll
        for (int k = 0; k < EPT; k++) {
            bool c = m2[k] >= theta_sel;
            unsigned bal = __ballot_sync(FULLM, c);
            if (bal) {
                int base = 0;
                if (lane == 0) base = atomicAdd(&cand_cnt, __popc(bal));
                base = __shfl_sync(FULLM, base, 0);
                if (c) {
                    int pos = base + __popc(bal & ((1u << lane) - 1u));
                    if (pos < CAP) { cand_idx[pos] = tid + k * NTHR; cand_val[pos] = m2[k]; }
                }
            }
        }
        __syncthreads();   // (B)

        // ================= P3: warp0 serial || others element math =========
        if (wid == 0) {
            int L = cand_cnt;
            if (L <= 32) {
                // count-rank: exact top-8 with lax.top_k tie semantics
                float v  = (lane < L) ? cand_val[lane] : -INFINITY;
                int   ix = (lane < L) ? cand_idx[lane] : 0x7fffffff;
                int rk = 0;
                for (int j = 0; j < L; j++) {
                    float vj = __shfl_sync(FULLM, v, j);
                    int   xj = __shfl_sync(FULLM, ix, j);
                    if (vj > v || (vj == v && xj < ix)) rk++;
                }
                if (lane < L && rk < KTOP) top_idx[rk] = ix;
            } else {
                // rare fallback: 8 knockout rounds over all 2048 (recompute m2)
                int sel[KTOP];
                for (int r = 0; r < KTOP; r++) {
                    float bv = -INFINITY; int bi = 0x7fffffff;
                    int e0 = lane * (DIMN / 32);
                    for (int q = 0; q < DIMN / 32; q++) {
                        int e = e0 + q;
                        bool skip = false;
                        for (int u = 0; u < r; u++) if (sel[u] == e) skip = true;
                        if (!skip) {
                            float h = sh_h[e];
                            float cr = h * s_re[e], ci2 = h * s_im[e];
                            float m = cr * cr + ci2 * ci2;
                            if (m > bv) { bv = m; bi = e; }
                        }
                    }
                    float v = bv; int ix = bi;
                    warp_argmax(v, ix);
                    sel[r] = ix;
                    if (lane == 0) top_idx[r] = ix;
                }
            }
            __syncwarp();

            // pair phase: score = Re(c_i * conj(c_j))
            int pci = 0, pcj = 0;
            float score = -INFINITY; bool pos = false;
            float sir = 0.f, sii = 0.f, sjr = 0.f, sji = 0.f;
            if (lane < NPAIR) {
                pci = top_idx[c_iu[lane]];
                pcj = top_idx[c_ju[lane]];
                float hi_ = sh_h[pci], hj_ = sh_h[pcj];
                sir = s_re[pci]; sii = s_im[pci];
                sjr = s_re[pcj]; sji = s_im[pcj];
                float cir = hi_ * sir, cii = hi_ * sii;
                float cjr = hj_ * sjr, cji = hj_ * sji;
                score = cir * cjr + cii * cji;
                pos = score > 0.f;
            }
            unsigned posb = __ballot_sync(FULLM, pos);
            int n_pos = __popc(posb);
            unsigned bound = 0u;
            float pmre = 0.f, pmim = 0.f;
            if (n_pos > 0) {
                int n_bind = max(1, (int)((float)n_pos * 0.15f));   // f32 trunc
                int th_idx = min(n_bind - 1, n_pos - 1);
                // count-rank among positive scores (replaces knockout loop)
                float sv = pos ? score : -INFINITY;
                int rk = 0;
#pragma unroll
                for (int j = 0; j < NPAIR; j++) {
                    float vj = __shfl_sync(FULLM, sv, j);
                    if (((posb >> j) & 1u) && (vj > sv || (vj == sv && j < lane))) rk++;
                }
                unsigned tb = __ballot_sync(FULLM, pos && (rk == th_idx));
                float theta = __shfl_sync(FULLM, sv, __ffs(tb) - 1);
                bound = __ballot_sync(FULLM, (lane < NPAIR) && (score >= theta));
            }
            if (lane < NPAIR) {
                float pr = sir * sjr - sii * sji;
                float pi = sir * sji + sii * sjr;
                float mag = sqrtf(pr * pr + pi * pi);
                float sc = 0.05f / fmaxf(mag, 1e-8f);
                pmre = pr * sc; pmim = pi * sc;
            }

            // sequential transient scan over bound pairs (ascending pair order)
            unsigned bmloop = bound;
            while (bmloop) {
                int p = __ffs(bmloop) - 1; bmloop &= bmloop - 1;
                int   bci = __shfl_sync(FULLM, pci,  p);
                int   bcj = __shfl_sync(FULLM, pcj,  p);
                float bmr = __shfl_sync(FULLM, pmre, p);
                float bmi = __shfl_sync(FULLM, pmim, p);
                bool act = (lane < MSLOT) && (t_cnt > 0);
                bool mat = act && ((t_ti == bci && t_tj == bcj) || (t_ti == bcj && t_tj == bci));
                unsigned mb = __ballot_sync(FULLM, mat);
                if (mb) {
                    if (lane == __ffs(mb) - 1) t_cnt = 5;           // refresh
                } else {
                    unsigned fb = __ballot_sync(FULLM, (lane < MSLOT) && t_cnt <= 0);
                    if (fb && lane == __ffs(fb) - 1) {              // insert at first free
                        t_ti = bci; t_tj = bcj; t_mre = bmr; t_mim = bmi; t_cnt = 5;
                    }
                }
            }

            // decay + liveness
            bool alive = false;
            if (lane < MSLOT) {
                t_mre *= 0.9f; t_mim *= 0.9f; t_cnt -= 1;
                alive = (t_cnt > 0) && (sqrtf(t_mre * t_mre + t_mim * t_mim) > 1e-6f);
                if (!alive) { t_cnt = 0; t_mre = 0.f; t_mim = 0.f; }
            }
            // endpoint mapping: lane l -> (slot l, ti), lane l+16 -> (slot l-16, tj)
            unsigned am = __ballot_sync(FULLM, alive);        // bits 0..15
            int slot = lane & 15;
            bool myact = ((am >> slot) & 1u) != 0u;
            int   tis = __shfl_sync(FULLM, t_ti,  slot);
            int   tjs = __shfl_sync(FULLM, t_tj,  slot);
            float mr  = __shfl_sync(FULLM, t_mre, slot);
            float mi  = __shfl_sync(FULLM, t_mim, slot);
            int eidx = (lane < 16) ? tis : tjs;
            if (myact) {
                atomicAdd(&d_re[eidx], 0.1f * mr);
                atomicAdd(&d_im[eidx], 0.1f * mi);
            }
            __syncwarp();
            // sparse corrections: one leader per unique affected index
            float dnorm = 0.f;
            unsigned actm = am | (am << 16);
            if (myact) {
                unsigned peers = __match_any_sync(actm, eidx);
                if ((__ffs(peers) - 1) == lane) {
                    float dre = d_re[eidx], dim = d_im[eidx];
                    float sr = s_re[eidx], si = s_im[eidx];
                    float h  = sh_h[eidx];
                    float tr = tb_re_g[eidx], tii = tb_im_g[eidx];
                    float a0, c0, a1, c1;
                    upd_elem(sr, si, 0.f, 0.f, h, tr, tii, eta, a0, c0);
                    upd_elem(sr, si, dre, dim, h, tr, tii, eta, a1, c1);
                    dnorm = (a1 * a1 + c1 * c1) - (a0 * a0 + c0 * c0);
                    d_re[eidx] = a1; d_im[eidx] = c1;   // corrected unnormalized value
                    atomicOr(&bmap[eidx >> 5], 1u << (eidx & 31));
                }
            }
#pragma unroll
            for (int off = 16; off; off >>= 1)
                dnorm += __shfl_xor_sync(FULLM, dnorm, off);
            if (lane == 0) red[NW] = dnorm;
        }

        // all warps (warps 1-15 run this concurrently with warp0's serial part)
        float nre[EPT], nim[EPT];
        float ps = 0.f;
#pragma unroll
        for (int k = 0; k < EPT; k++) {
            float a, c2;
            upd_elem(sre[k], sim[k], 0.f, 0.f, hv[k], tbr[k], tbi[k], eta, a, c2);
            nre[k] = a; nim[k] = c2;
            ps += a * a + c2 * c2;
        }
#pragma unroll
        for (int off = 16; off; off >>= 1) ps += __shfl_xor_sync(FULLM, ps, off);
        if (lane == 0) red[wid] = ps;
        __syncthreads();   // (C)

        // ================= P4: redundant norm sum + patch + write ==========
        float tot = (lane <= NW) ? red[lane] : 0.f;   // 17 values
#pragma unroll
        for (int off = 16; off; off >>= 1) tot += __shfl_xor_sync(FULLM, tot, off);
        float invn = 1.f / fmaxf(sqrtf(tot), 1e-8f);
#pragma unroll
        for (int k = 0; k < EPT; k++) {
            int e = tid + k * NTHR;
            unsigned w = bmap[e >> 5];
            float a, c2;
            if ((w >> (e & 31)) & 1u) {
                a = d_re[e]; c2 = d_im[e];
                d_re[e] = 0.f; d_im[e] = 0.f;                 // restore invariant
                atomicAnd(&bmap[e >> 5], ~(1u << (e & 31)));  // clear own bit
            } else {
                a = nre[k]; c2 = nim[k];
            }
            float em = a * a + c2 * c2;
            float fa = a * invn, fc = c2 * invn;
            sre[k] = fa; sim[k] = fc;
            s_re[e] = fa; s_im[e] = fc;
            ob[(size_t)t * DIMN + e] = sqrtf(em) * invn;      // |s_new|
        }
        // no barrier needed before next P1: next-step SMEM writes are
        // separated from this step's readers by barriers A/B.
    }
}

extern "C" void kernel_launch(void* const* d_in, const int* in_sizes, int n_in,
                              void* d_out, int out_size) {
    const float* x       = (const float*)d_in[0];
    const float* tape_re = (const float*)d_in[1];
    const float* tape_im = (const float*)d_in[2];
    const float* eta_p   = (const float*)d_in[3];
    const float* tb_re   = (const float*)d_in[4];
    const float* tb_im   = (const float*)d_in[5];
    float* out = (float*)d_out;

    int B = in_sizes[0] / (TSTEPS * DIMN);   // 64
    me_bind_kernel<<<B, NTHR>>>(x, tape_re, tape_im, eta_p, tb_re, tb_im, out);
}

// round 6
// speedup vs baseline: 1.4603x; 1.0637x over previous
#include <cuda_runtime.h>
#include <math.h>
#include <stdint.h>

// Problem constants (fixed by reference)
#define DIMN   2048
#define TSTEPS 256
#define KTOP   8
#define NPAIR  28
#define MSLOT  16
#define NDATA  512    // data threads
#define NTOT   544    // +1 serial warp
#define EPT    4      // 512*4 = 2048
#define NWD    16     // data warps
#define WCAP   32     // candidate slots per warp region
#define FULLM  0xffffffffu

#define SMEM_BYTES (72 * 1024)

// Upper-triangle pair tables, row-major (matches np.triu_indices(8, k=1))
__constant__ int c_iu[NPAIR] = {0,0,0,0,0,0,0,1,1,1,1,1,1,2,2,2,2,2,3,3,3,3,4,4,4,5,5,6};
__constant__ int c_ju[NPAIR] = {1,2,3,4,5,6,7,2,3,4,5,6,7,3,4,5,6,7,4,5,6,7,5,6,7,6,7,7};

__device__ __forceinline__ void warp_argmax(float& v, int& ix) {
#pragma unroll
    for (int off = 16; off; off >>= 1) {
        float ov = __shfl_xor_sync(FULLM, v, off);
        int   oi = __shfl_xor_sync(FULLM, ix, off);
        if (ov > v || (ov == v && oi < ix)) { v = ov; ix = oi; }
    }
}

// Shared update formula: warp-serial correction path and owners' zero-delta
// path must produce bit-identical results for identical inputs.
__device__ __forceinline__ void upd_elem(float sr, float si, float dr, float di,
                                         float h, float tr, float tii, float eta,
                                         float& a, float& c) {
    float rc = h * (sr + dr), ic = h * (si + di);
    float aic = fabsf(ic);
    bool res = (rc >  1e-6f) && (aic <  rc);
    bool tor = (rc < -1e-6f) || (aic >= fabsf(rc));
    float kf = (res || tor) ? 1.f : 0.f;   // res & tor mutually exclusive
    float tf = tor ? 1.f : 0.f;
    a = sr + eta * (rc * kf + tf * tr);
    c = si + eta * (ic * kf + tf * tii);
}

__device__ __forceinline__ void cp_async16(void* dst_smem, const void* src) {
    unsigned u = (unsigned)__cvta_generic_to_shared(dst_smem);
    asm volatile("cp.async.cg.shared.global [%0], [%1], 16;" :: "r"(u), "l"(src));
}
#define CP_COMMIT() asm volatile("cp.async.commit_group;")
#define CP_WAIT0()  asm volatile("cp.async.wait_group 0;")

__global__ __launch_bounds__(NTOT, 1)
void me_bind_kernel(const float* __restrict__ x,
                    const float* __restrict__ tape_re,
                    const float* __restrict__ tape_im,
                    const float* __restrict__ eta_p,
                    const float* __restrict__ tb_re_g,
                    const float* __restrict__ tb_im_g,
                    float* __restrict__ out)
{
    extern __shared__ char smem_raw[];
    float* s_re   = (float*)smem_raw;            // [DIMN]
    float* s_im   = s_re + DIMN;                 // [DIMN]
    float* d_re   = s_im + DIMN;                 // [DIMN] sparse delta / corrected
    float* d_im   = d_re + DIMN;                 // [DIMN]
    float* hbuf   = d_im + DIMN;                 // [2][DIMN] double-buffered h
    float* tbres  = hbuf + 2 * DIMN;             // [DIMN]
    float* tbims  = tbres + DIMN;                // [DIMN]
    float* cand_val = tbims + DIMN;              // [NWD*WCAP]
    int*   cand_idx = (int*)(cand_val + NWD * WCAP);
    int*   wcnt   = cand_idx + NWD * WCAP;       // [NWD] true counts
    float* wmax   = (float*)(wcnt + NWD);        // [NWD]
    int*   top_idx = (int*)(wmax + NWD);         // [KTOP]
    float* red    = (float*)(top_idx + KTOP);    // [NWD+1]
    unsigned* bmap = (unsigned*)(red + NWD + 1); // [DIMN/32]

    const int tid  = threadIdx.x;
    const int lane = tid & 31;
    const int wid  = tid >> 5;
    const bool is_data = (wid < NWD);
    const int b    = blockIdx.x;
    const float eta = fabsf(eta_p[0]);

    // transient table: serial-warp lanes 0..15, one slot per lane, registers
    int   t_ti = 0, t_tj = 0, t_cnt = 0;
    float t_mre = 0.f, t_mim = 0.f;

    float sre[EPT], sim[EPT], tbr[EPT], tbi[EPT];

    const float* xb = x + (size_t)b * TSTEPS * DIMN;
    float*       ob = out + (size_t)b * TSTEPS * DIMN;

    // ---- init: s0 = renorm(tape) + SMEM mirrors + h prefetch for t=0 ----
    float psum = 0.f;
    if (is_data) {
#pragma unroll
        for (int k = 0; k < EPT; k++) {
            int e = tid + k * NDATA;
            float a = tape_re[e], c = tape_im[e];
            sre[k] = a; sim[k] = c;
            psum += a * a + c * c;
            float tr = tb_re_g[e], ti_ = tb_im_g[e];
            tbr[k] = tr; tbi[k] = ti_;
            tbres[e] = tr; tbims[e] = ti_;
            d_re[e] = 0.f; d_im[e] = 0.f;
        }
        // stream h row 0 into hbuf[0]
        cp_async16(hbuf + tid * 4, xb + tid * 4);
    }
    CP_COMMIT();
    if (tid < DIMN / 32) bmap[tid] = 0u;
    {
#pragma unroll
        for (int off = 16; off; off >>= 1) psum += __shfl_xor_sync(FULLM, psum, off);
        if (is_data && lane == 0) red[wid] = psum;
        CP_WAIT0();
        __syncthreads();
        float tot = 0.f;
        if (lane < NWD) tot = red[lane];
#pragma unroll
        for (int off = 16; off; off >>= 1) tot += __shfl_xor_sync(FULLM, tot, off);
        float inv = 1.f / fmaxf(sqrtf(tot), 1e-8f);
        if (is_data) {
#pragma unroll
            for (int k = 0; k < EPT; k++) {
                int e = tid + k * NDATA;
                sre[k] *= inv; sim[k] *= inv;
                s_re[e] = sre[k]; s_im[e] = sim[k];
            }
        }
    }
    __syncthreads();

    for (int t = 0; t < TSTEPS; t++) {
        float* hb = hbuf + (t & 1) * DIMN;

        // ================= P1: h from SMEM, m2, per-warp max; prefetch t+1 ==
        float hv[EPT], m2[EPT];
        if (is_data) {
            float wmx = -INFINITY;
#pragma unroll
            for (int k = 0; k < EPT; k++) {
                int e = tid + k * NDATA;
                float h = hb[e];
                hv[k] = h;
                float cr = h * sre[k], ci_ = h * sim[k];
                m2[k] = cr * cr + ci_ * ci_;
                wmx = fmaxf(wmx, m2[k]);
            }
            if (t + 1 < TSTEPS)
                cp_async16(hbuf + ((t + 1) & 1) * DIMN + tid * 4,
                           xb + (size_t)(t + 1) * DIMN + tid * 4);
#pragma unroll
            for (int off = 16; off; off >>= 1)
                wmx = fmaxf(wmx, __shfl_xor_sync(FULLM, wmx, off));
            if (lane == 0) wmax[wid] = wmx;
        }
        CP_COMMIT();
        __syncthreads();   // (A)

        // ================= P2: theta (redundant) + per-warp-region compaction
        if (is_data) {
            float theta_sel;
            {
                float v = (lane < NWD) ? wmax[lane] : -INFINITY;
                int rk = 0;
#pragma unroll
                for (int j = 0; j < NWD; j++) {
                    float vj = __shfl_sync(FULLM, v, j);
                    if (vj > v || (vj == v && j < lane)) rk++;
                }
                unsigned b8 = __ballot_sync(FULLM, (lane < NWD) && (rk == KTOP - 1));
                theta_sel = __shfl_sync(FULLM, v, __ffs(b8) - 1);
            }
            int cnt = 0;
            const int base = wid * WCAP;
#pragma unroll
            for (int k = 0; k < EPT; k++) {
                bool c = m2[k] >= theta_sel;
                unsigned bal = __ballot_sync(FULLM, c);
                if (c) {
                    int pos = cnt + __popc(bal & ((1u << lane) - 1u));
                    if (pos < WCAP) {
                        cand_idx[base + pos] = tid + k * NDATA;
                        cand_val[base + pos] = m2[k];
                    }
                }
                cnt += __popc(bal);
            }
            if (lane == 0) wcnt[wid] = cnt;   // true count (may exceed WCAP)
        }
        __syncthreads();   // (B)

        // ===== P3: serial warp (pairs/transients) || data warps (elem math) =
        if (!is_data) {
            // ---- gather candidates via packed prefix scan ----
            int c = (lane < NWD) ? wcnt[lane] : 0;
            int pk = c;                        // inclusive scan of counts
#pragma unroll
            for (int off = 1; off < 32; off <<= 1) {
                int o = __shfl_up_sync(FULLM, pk, off);
                if (lane >= off) pk += o;
            }
            int excl = pk - c;
            int L = __shfl_sync(FULLM, pk, NWD - 1);
            int packed = (excl << 16) | c;     // both < 2^15

            if (L <= 32) {
                int srcw = -1, srcm = 0;
#pragma unroll
                for (int w = 0; w < NWD; w++) {
                    int pw = __shfl_sync(FULLM, packed, w);
                    int Pw = pw >> 16, cw = pw & 0xffff;
                    if (lane >= Pw && lane < Pw + cw) { srcw = w; srcm = lane - Pw; }
                }
                float v = -INFINITY; int ix = 0x7fffffff;
                if (srcw >= 0) {
                    v  = cand_val[srcw * WCAP + srcm];
                    ix = cand_idx[srcw * WCAP + srcm];
                }
                int rk = 0;
#pragma unroll
                for (int j = 0; j < 32; j++) {
                    float vj = __shfl_sync(FULLM, v, j);
                    int   xj = __shfl_sync(FULLM, ix, j);
                    if (vj > v || (vj == v && xj < ix)) rk++;
                }
                if (srcw >= 0 && rk < KTOP) top_idx[rk] = ix;
            } else {
                // rare fallback: 8 knockout rounds over all 2048
                int sel[KTOP];
                for (int r = 0; r < KTOP; r++) {
                    float bv = -INFINITY; int bi = 0x7fffffff;
                    int e0 = lane * (DIMN / 32);
                    for (int q = 0; q < DIMN / 32; q++) {
                        int e = e0 + q;
                        bool skip = false;
                        for (int u = 0; u < r; u++) if (sel[u] == e) skip = true;
                        if (!skip) {
                            float h = hb[e];
                            float cr = h * s_re[e], ci2 = h * s_im[e];
                            float m = cr * cr + ci2 * ci2;
                            if (m > bv) { bv = m; bi = e; }
                        }
                    }
                    float v = bv; int ix = bi;
                    warp_argmax(v, ix);
                    sel[r] = ix;
                    if (lane == 0) top_idx[r] = ix;
                }
            }
            __syncwarp();

            // ---- pair phase: score = Re(c_i * conj(c_j)) ----
            int pci = 0, pcj = 0;
            float score = -INFINITY; bool pos = false;
            float sir = 0.f, sii = 0.f, sjr = 0.f, sji = 0.f;
            if (lane < NPAIR) {
                pci = top_idx[c_iu[lane]];
                pcj = top_idx[c_ju[lane]];
                float hi_ = hb[pci], hj_ = hb[pcj];
                sir = s_re[pci]; sii = s_im[pci];
                sjr = s_re[pcj]; sji = s_im[pcj];
                float cir = hi_ * sir, cii = hi_ * sii;
                float cjr = hj_ * sjr, cji = hj_ * sji;
                score = cir * cjr + cii * cji;
                pos = score > 0.f;
            }
            unsigned posb = __ballot_sync(FULLM, pos);
            int n_pos = __popc(posb);
            unsigned bound = 0u;
            float pmre = 0.f, pmim = 0.f;
            if (n_pos > 0) {
                int n_bind = max(1, (int)((float)n_pos * 0.15f));   // f32 trunc
                int th_idx = min(n_bind - 1, n_pos - 1);
                float sv = pos ? score : -INFINITY;
                int rk = 0;
#pragma unroll
                for (int j = 0; j < NPAIR; j++) {
                    float vj = __shfl_sync(FULLM, sv, j);
                    if (((posb >> j) & 1u) && (vj > sv || (vj == sv && j < lane))) rk++;
                }
                unsigned tb = __ballot_sync(FULLM, pos && (rk == th_idx));
                float theta = __shfl_sync(FULLM, sv, __ffs(tb) - 1);
                bound = __ballot_sync(FULLM, (lane < NPAIR) && (score >= theta));
            }
            if (lane < NPAIR) {
                float pr = sir * sjr - sii * sji;
                float pi = sir * sji + sii * sjr;
                float mag = sqrtf(pr * pr + pi * pi);
                float sc = 0.05f / fmaxf(mag, 1e-8f);
                pmre = pr * sc; pmim = pi * sc;
            }

            // ---- sequential transient scan over bound pairs ----
            unsigned bmloop = bound;
            while (bmloop) {
                int p = __ffs(bmloop) - 1; bmloop &= bmloop - 1;
                int   bci = __shfl_sync(FULLM, pci,  p);
                int   bcj = __shfl_sync(FULLM, pcj,  p);
                float bmr = __shfl_sync(FULLM, pmre, p);
                float bmi = __shfl_sync(FULLM, pmim, p);
                bool act = (lane < MSLOT) && (t_cnt > 0);
                bool mat = act && ((t_ti == bci && t_tj == bcj) || (t_ti == bcj && t_tj == bci));
                unsigned mb = __ballot_sync(FULLM, mat);
                if (mb) {
                    if (lane == __ffs(mb) - 1) t_cnt = 5;           // refresh
                } else {
                    unsigned fb = __ballot_sync(FULLM, (lane < MSLOT) && t_cnt <= 0);
                    if (fb && lane == __ffs(fb) - 1) {              // insert
                        t_ti = bci; t_tj = bcj; t_mre = bmr; t_mim = bmi; t_cnt = 5;
                    }
                }
            }

            // ---- decay + liveness ----
            bool alive = false;
            if (lane < MSLOT) {
                t_mre *= 0.9f; t_mim *= 0.9f; t_cnt -= 1;
                alive = (t_cnt > 0) && (sqrtf(t_mre * t_mre + t_mim * t_mim) > 1e-6f);
                if (!alive) { t_cnt = 0; t_mre = 0.f; t_mim = 0.f; }
            }
            // endpoint mapping: lane l -> (slot l, ti), lane l+16 -> (slot l-16, tj)
            unsigned am = __ballot_sync(FULLM, alive);        // bits 0..15
            int slot = lane & 15;
            bool myact = ((am >> slot) & 1u) != 0u;
            int   tis = __shfl_sync(FULLM, t_ti,  slot);
            int   tjs = __shfl_sync(FULLM, t_tj,  slot);
            float mr  = __shfl_sync(FULLM, t_mre, slot);
            float mi  = __shfl_sync(FULLM, t_mim, slot);
            int eidx = (lane < 16) ? tis : tjs;
            if (myact) {
                atomicAdd(&d_re[eidx], 0.1f * mr);
                atomicAdd(&d_im[eidx], 0.1f * mi);
            }
            __syncwarp();
            // ---- sparse corrections: one leader per unique affected index ----
            float dnorm = 0.f;
            unsigned actm = am | (am << 16);
            if (myact) {
                unsigned peers = __match_any_sync(actm, eidx);
                if ((__ffs(peers) - 1) == lane) {
                    float dre = d_re[eidx], dim = d_im[eidx];
                    float sr = s_re[eidx], si = s_im[eidx];
                    float h  = hb[eidx];
                    float tr = tbres[eidx], tii = tbims[eidx];
                    float a0, c0, a1, c1;
                    upd_elem(sr, si, 0.f, 0.f, h, tr, tii, eta, a0, c0);
                    upd_elem(sr, si, dre, dim, h, tr, tii, eta, a1, c1);
                    dnorm = (a1 * a1 + c1 * c1) - (a0 * a0 + c0 * c0);
                    d_re[eidx] = a1; d_im[eidx] = c1;   // corrected unnormalized value
                    atomicOr(&bmap[eidx >> 5], 1u << (eidx & 31));
                }
            }
#pragma unroll
            for (int off = 16; off; off >>= 1)
                dnorm += __shfl_xor_sync(FULLM, dnorm, off);
            if (lane == 0) red[NWD] = dnorm;
        }

        // data warps: element math, overlapped with the serial warp
        float nre[EPT], nim[EPT];
        if (is_data) {
            float ps = 0.f;
#pragma unroll
            for (int k = 0; k < EPT; k++) {
                float a, c2;
                upd_elem(sre[k], sim[k], 0.f, 0.f, hv[k], tbr[k], tbi[k], eta, a, c2);
                nre[k] = a; nim[k] = c2;
                ps += a * a + c2 * c2;
            }
#pragma unroll
            for (int off = 16; off; off >>= 1) ps += __shfl_xor_sync(FULLM, ps, off);
            if (lane == 0) red[wid] = ps;
        }
        CP_WAIT0();        // h(t+1) copy landed (issued at P1, ~full phase ago)
        __syncthreads();   // (C)

        // ================= P4: redundant norm + patch + write (data only) ===
        if (is_data) {
            float tot = (lane <= NWD) ? red[lane] : 0.f;   // 17 values
#pragma unroll
            for (int off = 16; off; off >>= 1) tot += __shfl_xor_sync(FULLM, tot, off);
            float invn = 1.f / fmaxf(sqrtf(tot), 1e-8f);
#pragma unroll
            for (int k = 0; k < EPT; k++) {
                int e = tid + k * NDATA;
                unsigned w = bmap[e >> 5];
                float a, c2;
                if ((w >> (e & 31)) & 1u) {
                    a = d_re[e]; c2 = d_im[e];
                    d_re[e] = 0.f; d_im[e] = 0.f;                 // restore invariant
                    atomicAnd(&bmap[e >> 5], ~(1u << (e & 31)));  // clear own bit
                } else {
                    a = nre[k]; c2 = nim[k];
                }
                float em = a * a + c2 * c2;
                float fa = a * invn, fc = c2 * invn;
                sre[k] = fa; sim[k] = fc;
                s_re[e] = fa; s_im[e] = fc;
                ob[(size_t)t * DIMN + e] = sqrtf(em) * invn;      // |s_new|
            }
        }
        // no trailing barrier: next step's SMEM writes are separated from this
        // step's readers by barriers A/B (same argument as prior rounds).
    }
}

extern "C" void kernel_launch(void* const* d_in, const int* in_sizes, int n_in,
                              void* d_out, int out_size) {
    const float* x       = (const float*)d_in[0];
    const float* tape_re = (const float*)d_in[1];
    const float* tape_im = (const float*)d_in[2];
    const float* eta_p   = (const float*)d_in[3];
    const float* tb_re   = (const float*)d_in[4];
    const float* tb_im   = (const float*)d_in[5];
    float* out = (float*)d_out;

    static int attr_done = 0;
    if (!attr_done) {
        cudaFuncSetAttribute(me_bind_kernel,
                             cudaFuncAttributeMaxDynamicSharedMemorySize, SMEM_BYTES);
        attr_done = 1;
    }
    int B = in_sizes[0] / (TSTEPS * DIMN);   // 64
    me_bind_kernel<<<B, NTOT, SMEM_BYTES>>>(x, tape_re, tape_im, eta_p, tb_re, tb_im, out);
}

// round 8
// speedup vs baseline: 1.5010x; 1.0279x over previous
#include <cuda_runtime.h>
#include <math.h>
#include <stdint.h>

// Problem constants (fixed by reference)
#define DIMN   2048
#define TSTEPS 256
#define KTOP   8
#define NPAIR  28
#define MSLOT  16
#define NDATA  512    // data threads
#define NTOT   544    // +1 serial warp
#define EPT    4      // 512*4 = 2048, contiguous per thread
#define NWD    16     // data warps
#define WCAP   32     // candidate slots per warp region
#define FULLM  0xffffffffu

#define SMEM_BYTES (72 * 1024)

// Upper-triangle pair tables, row-major (matches np.triu_indices(8, k=1))
__constant__ int c_iu[NPAIR] = {0,0,0,0,0,0,0,1,1,1,1,1,1,2,2,2,2,2,3,3,3,3,4,4,4,5,5,6};
__constant__ int c_ju[NPAIR] = {1,2,3,4,5,6,7,2,3,4,5,6,7,3,4,5,6,7,4,5,6,7,5,6,7,6,7,7};

__device__ __forceinline__ void warp_argmax(float& v, int& ix) {
#pragma unroll
    for (int off = 16; off; off >>= 1) {
        float ov = __shfl_xor_sync(FULLM, v, off);
        int   oi = __shfl_xor_sync(FULLM, ix, off);
        if (ov > v || (ov == v && oi < ix)) { v = ov; ix = oi; }
    }
}

// Shared update formula: serial correction path and owners' zero-delta path
// must produce (near-)identical results; only norm ulps differ if FMA fusion
// diverges between call sites (within 1e-3 tolerance by a wide margin).
__device__ __forceinline__ void upd_elem(float sr, float si, float dr, float di,
                                         float h, float tr, float tii, float eta,
                                         float& a, float& c) {
    float rc = h * (sr + dr), ic = h * (si + di);
    float aic = fabsf(ic);
    bool res = (rc >  1e-6f) && (aic <  rc);
    bool tor = (rc < -1e-6f) || (aic >= fabsf(rc));
    float kf = (res || tor) ? 1.f : 0.f;   // res & tor mutually exclusive
    float tf = tor ? 1.f : 0.f;
    a = sr + eta * (rc * kf + tf * tr);
    c = si + eta * (ic * kf + tf * tii);
}

__device__ __forceinline__ void cp_async16(void* dst_smem, const void* src) {
    unsigned u = (unsigned)__cvta_generic_to_shared(dst_smem);
    asm volatile("cp.async.cg.shared.global [%0], [%1], 16;" :: "r"(u), "l"(src));
}
#define CP_COMMIT() asm volatile("cp.async.commit_group;")
#define CP_WAIT0()  asm volatile("cp.async.wait_group 0;")

__device__ __forceinline__ void st_release_s32(int* p, int v) {
    unsigned u = (unsigned)__cvta_generic_to_shared(p);
    asm volatile("st.release.cta.shared.b32 [%0], %1;" :: "r"(u), "r"(v) : "memory");
}
__device__ __forceinline__ int ld_acquire_s32(int* p) {
    unsigned u = (unsigned)__cvta_generic_to_shared(p);
    int v;
    asm volatile("ld.acquire.cta.shared.b32 %0, [%1];" : "=r"(v) : "r"(u) : "memory");
    return v;
}

__global__ __launch_bounds__(NTOT, 1)
void me_bind_kernel(const float* __restrict__ x,
                    const float* __restrict__ tape_re,
                    const float* __restrict__ tape_im,
                    const float* __restrict__ eta_p,
                    const float* __restrict__ tb_re_g,
                    const float* __restrict__ tb_im_g,
                    float* __restrict__ out)
{
    extern __shared__ char smem_raw[];
    float* s_re   = (float*)smem_raw;            // [DIMN]
    float* s_im   = s_re + DIMN;                 // [DIMN]
    float* d_re   = s_im + DIMN;                 // [DIMN] sparse delta / corrected
    float* d_im   = d_re + DIMN;                 // [DIMN]
    float* hbuf   = d_im + DIMN;                 // [2][DIMN] double-buffered h
    float* tbres  = hbuf + 2 * DIMN;             // [DIMN]
    float* tbims  = tbres + DIMN;                // [DIMN]
    float* cand_val = tbims + DIMN;              // [NWD*WCAP]
    int*   cand_idx = (int*)(cand_val + NWD * WCAP);
    int*   wcnt   = cand_idx + NWD * WCAP;       // [NWD]
    int*   wflag  = wcnt + NWD;                  // [NWD] step-tagged publish flags
    float* wmax   = (float*)(wflag + NWD);       // [NWD]
    int*   top_idx = (int*)(wmax + NWD);         // [KTOP]
    float* red    = (float*)(top_idx + KTOP);    // [NWD+1]
    float* rankv  = red + NWD + 1;               // [32] rank staging
    int*   ranki  = (int*)(rankv + 32);          // [32]
    unsigned* bmap = (unsigned*)(ranki + 32);    // [DIMN/32]

    const int tid  = threadIdx.x;
    const int lane = tid & 31;
    const int wid  = tid >> 5;
    const bool is_data = (wid < NWD);
    const int b    = blockIdx.x;
    const int eb   = tid * EPT;                  // contiguous element base
    const float eta = fabsf(eta_p[0]);

    // transient table: serial-warp lanes 0..15, one slot per lane, registers
    int   t_ti = 0, t_tj = 0, t_cnt = 0;
    float t_mre = 0.f, t_mim = 0.f;

    float sre[EPT], sim[EPT], tbr[EPT], tbi[EPT];

    const float* xb = x + (size_t)b * TSTEPS * DIMN;
    float*       ob = out + (size_t)b * TSTEPS * DIMN;

    // ---- init: s0 = renorm(tape) + SMEM mirrors + h(0) stream ----
    float psum = 0.f;
    if (is_data) {
        float4 tre = *(const float4*)(tape_re + eb);
        float4 tim = *(const float4*)(tape_im + eb);
        float4 br  = *(const float4*)(tb_re_g + eb);
        float4 bi  = *(const float4*)(tb_im_g + eb);
        sre[0]=tre.x; sre[1]=tre.y; sre[2]=tre.z; sre[3]=tre.w;
        sim[0]=tim.x; sim[1]=tim.y; sim[2]=tim.z; sim[3]=tim.w;
        tbr[0]=br.x;  tbr[1]=br.y;  tbr[2]=br.z;  tbr[3]=br.w;
        tbi[0]=bi.x;  tbi[1]=bi.y;  tbi[2]=bi.z;  tbi[3]=bi.w;
#pragma unroll
        for (int k = 0; k < EPT; k++) psum += sre[k]*sre[k] + sim[k]*sim[k];
        *(float4*)(tbres + eb) = br;
        *(float4*)(tbims + eb) = bi;
        *(float4*)(d_re + eb) = make_float4(0.f,0.f,0.f,0.f);
        *(float4*)(d_im + eb) = make_float4(0.f,0.f,0.f,0.f);
        cp_async16(hbuf + eb, xb + eb);
        CP_COMMIT();
    }
    if (tid < DIMN / 32) bmap[tid] = 0u;
    if (tid < NWD) wflag[tid] = 0;
    {
#pragma unroll
        for (int off = 16; off; off >>= 1) psum += __shfl_xor_sync(FULLM, psum, off);
        if (is_data && lane == 0) red[wid] = psum;
        if (is_data) CP_WAIT0();
        __syncthreads();
        float tot = (lane < NWD) ? red[lane] : 0.f;
#pragma unroll
        for (int off = 16; off; off >>= 1) tot += __shfl_xor_sync(FULLM, tot, off);
        float inv = 1.f / fmaxf(sqrtf(tot), 1e-8f);
        if (is_data) {
#pragma unroll
            for (int k = 0; k < EPT; k++) { sre[k] *= inv; sim[k] *= inv; }
            *(float4*)(s_re + eb) = make_float4(sre[0],sre[1],sre[2],sre[3]);
            *(float4*)(s_im + eb) = make_float4(sim[0],sim[1],sim[2],sim[3]);
        }
    }
    __syncthreads();

    for (int t = 0; t < TSTEPS; t++) {
        float* hb = hbuf + (t & 1) * DIMN;

        float cr[EPT], ci2[EPT], m2[EPT];
        if (is_data) {
            // ============ P1: h (LDS.128), m2, warp max via REDUX ============
            float4 hq = *(float4*)(hb + eb);
            float hv[EPT] = {hq.x, hq.y, hq.z, hq.w};
#pragma unroll
            for (int k = 0; k < EPT; k++) {
                cr[k] = hv[k] * sre[k]; ci2[k] = hv[k] * sim[k];
                m2[k] = cr[k]*cr[k] + ci2[k]*ci2[k];
            }
            if (t + 1 < TSTEPS) {
                cp_async16(hbuf + ((t + 1) & 1) * DIMN + eb,
                           xb + (size_t)(t + 1) * DIMN + eb);
                CP_COMMIT();
            }
            float lm = fmaxf(fmaxf(m2[0], m2[1]), fmaxf(m2[2], m2[3]));
            unsigned wm = __reduce_max_sync(FULLM, __float_as_uint(lm)); // m2>=0
            if (lane == 0) wmax[wid] = __uint_as_float(wm);
        }
        __syncthreads();   // (A)

        if (is_data) {
            // ============ P2: theta via LDS loop + compaction + publish ======
            float v = (lane < NWD) ? wmax[lane] : -INFINITY;
            int rk = 0;
#pragma unroll
            for (int j = 0; j < NWD; j++) {
                float vj = wmax[j];
                if (vj > v || (vj == v && j < lane)) rk++;
            }
            unsigned b8 = __ballot_sync(FULLM, (lane < NWD) && (rk == KTOP - 1));
            float theta_sel = __shfl_sync(FULLM, v, __ffs(b8) - 1);

            int cnt = 0;
            const int base = wid * WCAP;
#pragma unroll
            for (int k = 0; k < EPT; k++) {
                bool c = m2[k] >= theta_sel;
                unsigned bal = __ballot_sync(FULLM, c);
                if (c) {
                    int pos = cnt + __popc(bal & ((1u << lane) - 1u));
                    if (pos < WCAP) {
                        cand_idx[base + pos] = eb + k;
                        cand_val[base + pos] = m2[k];
                    }
                }
                cnt += __popc(bal);
            }
            if (lane == 0) {
                wcnt[wid] = cnt;                 // plain STS, then release flag
                st_release_s32(&wflag[wid], t + 1);
            }

            // ============ elem math (overlaps serial warp) ===================
            float nre_[EPT], nim_[EPT];
            float ps = 0.f;
#pragma unroll
            for (int k = 0; k < EPT; k++) {
                float rc = cr[k], ic = ci2[k];
                float aic = fabsf(ic);
                bool res = (rc >  1e-6f) && (aic <  rc);
                bool tor = (rc < -1e-6f) || (aic >= fabsf(rc));
                float kf = (res || tor) ? 1.f : 0.f;
                float tf = tor ? 1.f : 0.f;
                float a  = sre[k] + eta * (rc * kf + tf * tbr[k]);
                float c2 = sim[k] + eta * (ic * kf + tf * tbi[k]);
                nre_[k] = a; nim_[k] = c2;
                ps += a * a + c2 * c2;
            }
#pragma unroll
            for (int off = 16; off; off >>= 1) ps += __shfl_xor_sync(FULLM, ps, off);
            if (lane == 0) red[wid] = ps;
            CP_WAIT0();
            __syncthreads();   // (C)

            // ============ P4: norm + patch + vector write ====================
            float tot = (lane <= NWD) ? red[lane] : 0.f;
#pragma unroll
            for (int off = 16; off; off >>= 1) tot += __shfl_xor_sync(FULLM, tot, off);
            float invn = 1.f / fmaxf(sqrtf(tot), 1e-8f);

            unsigned w = bmap[tid >> 3];
            unsigned nib = (w >> ((tid & 7) * 4)) & 0xFu;
            if (nib) {
#pragma unroll
                for (int k = 0; k < EPT; k++) {
                    if ((nib >> k) & 1u) {
                        int e = eb + k;
                        nre_[k] = d_re[e]; nim_[k] = d_im[e];
                        d_re[e] = 0.f; d_im[e] = 0.f;
                    }
                }
                atomicAnd(&bmap[tid >> 3], ~(nib << ((tid & 7) * 4)));
            }
            float4 fo, fr, fi;
#pragma unroll
            for (int k = 0; k < EPT; k++) {
                float a = nre_[k], c2 = nim_[k];
                float em = a * a + c2 * c2;
                float fa = a * invn, fc = c2 * invn;
                sre[k] = fa; sim[k] = fc;
                ((float*)&fr)[k] = fa;
                ((float*)&fi)[k] = fc;
                ((float*)&fo)[k] = sqrtf(em) * invn;
            }
            *(float4*)(s_re + eb) = fr;
            *(float4*)(s_im + eb) = fi;
            *(float4*)(ob + (size_t)t * DIMN + eb) = fo;
        } else {
            // =================== serial warp ================================
            // acquire-poll all 16 publish flags (all lanes poll; lane&15)
            {
                int tag = t + 1;
                int* fp = &wflag[lane & 15];
                while (ld_acquire_s32(fp) != tag) {}
            }
            // ---- gather: prefix walk over wcnt (LDS broadcast) ----
            int L = 0, srcw = -1, srcm = 0;
#pragma unroll
            for (int w2 = 0; w2 < NWD; w2++) {
                int cw = wcnt[w2];
                if (lane >= L && lane < L + cw) { srcw = w2; srcm = lane - L; }
                L += cw;
            }

            if (L <= 32) {
                float v = -INFINITY; int ix = 0x7fffffff;
                if (srcw >= 0) {
                    v  = cand_val[srcw * WCAP + srcm];
                    ix = cand_idx[srcw * WCAP + srcm];
                }
                rankv[lane] = v; ranki[lane] = ix;
                __syncwarp();
                int rk = 0;
#pragma unroll
                for (int j = 0; j < 32; j++) {
                    float vj = rankv[j]; int xj = ranki[j];
                    if (vj > v || (vj == v && xj < ix)) rk++;
                }
                if (srcw >= 0 && rk < KTOP) top_idx[rk] = ix;
            } else {
                // rare fallback: 8 knockout rounds over all 2048
                int sel[KTOP];
                for (int r = 0; r < KTOP; r++) {
                    float bv = -INFINITY; int bi = 0x7fffffff;
                    int e0 = lane * (DIMN / 32);
                    for (int q = 0; q < DIMN / 32; q++) {
                        int e = e0 + q;
                        bool skip = false;
                        for (int u = 0; u < r; u++) if (sel[u] == e) skip = true;
                        if (!skip) {
                            float h = hb[e];
                            float crr = h * s_re[e], cii = h * s_im[e];
                            float m = crr * crr + cii * cii;
                            if (m > bv) { bv = m; bi = e; }
                        }
                    }
                    float v = bv; int ix = bi;
                    warp_argmax(v, ix);
                    sel[r] = ix;
                    if (lane == 0) top_idx[r] = ix;
                }
            }
            __syncwarp();

            // ---- pair phase ----
            int pci = 0, pcj = 0;
            float score = -INFINITY; bool pos = false;
            float sir = 0.f, sii = 0.f, sjr = 0.f, sji = 0.f;
            if (lane < NPAIR) {
                pci = top_idx[c_iu[lane]];
                pcj = top_idx[c_ju[lane]];
                float hi_ = hb[pci], hj_ = hb[pcj];
                sir = s_re[pci]; sii = s_im[pci];
                sjr = s_re[pcj]; sji = s_im[pcj];
                float cir = hi_ * sir, cii = hi_ * sii;
                float cjr = hj_ * sjr, cji = hj_ * sji;
                score = cir * cjr + cii * cji;
                pos = score > 0.f;
            }
            unsigned posb = __ballot_sync(FULLM, pos);
            int n_pos = __popc(posb);
            unsigned bound = 0u;
            float pmre = 0.f, pmim = 0.f;
            {
                float sv = pos ? score : -INFINITY;
                rankv[lane] = sv;
                __syncwarp();
                if (n_pos > 0) {
                    int n_bind = max(1, (int)((float)n_pos * 0.15f));   // f32 trunc
                    int th_idx = min(n_bind - 1, n_pos - 1);
                    int rk2 = 0;
#pragma unroll
                    for (int j = 0; j < NPAIR; j++) {
                        float vj = rankv[j];
                        if (((posb >> j) & 1u) && (vj > sv || (vj == sv && j < lane))) rk2++;
                    }
                    unsigned tb = __ballot_sync(FULLM, pos && (rk2 == th_idx));
                    float theta = __shfl_sync(FULLM, sv, __ffs(tb) - 1);
                    bound = __ballot_sync(FULLM, (lane < NPAIR) && (score >= theta));
                }
            }
            if (lane < NPAIR) {
                float pr = sir * sjr - sii * sji;
                float pi = sir * sji + sii * sjr;
                float mag = sqrtf(pr * pr + pi * pi);
                float sc = 0.05f / fmaxf(mag, 1e-8f);
                pmre = pr * sc; pmim = pi * sc;
            }

            // ---- PARALLEL transient update (== sequential 28-pair scan) ----
            // Lemma: a slot inserted this step never shares a key with a
            // pre-existing active slot (else the inserting pair would have
            // matched it); so duplicates only refresh-no-op inserted slots.
            {
                unsigned A0 = __ballot_sync(FULLM, (lane < MSLOT) && (t_cnt > 0)) & 0xffffu;
                bool isb = (lane < NPAIR) && ((bound >> lane) & 1u);
                unsigned mypack = (unsigned)pci | ((unsigned)pcj << 16);
                unsigned myrev  = (unsigned)pcj | ((unsigned)pci << 16);
                unsigned spack  = (unsigned)t_ti | ((unsigned)t_tj << 16);
                unsigned mm = 0u;
#pragma unroll
                for (int s2 = 0; s2 < MSLOT; s2++) {
                    unsigned sp = __shfl_sync(FULLM, spack, s2);
                    bool m = isb && ((A0 >> s2) & 1u) && (sp == mypack || sp == myrev);
                    mm |= m ? (1u << s2) : 0u;
                }
                // refresh = union over pairs of the LOWEST matching slot
                unsigned refresh = __reduce_or_sync(FULLM, mm & (0u - mm));
                bool icand = isb && (mm == 0u);
                unsigned mykey = (unsigned)min(pci, pcj) | ((unsigned)max(pci, pcj) << 16);
                unsigned gkey = icand ? mykey : (0x80000000u | (unsigned)lane);
                unsigned grp = __match_any_sync(FULLM, gkey);
                bool leader = icand && ((int)(__ffs(grp) - 1) == lane);
                unsigned lmask = __ballot_sync(FULLM, leader);
                int nL = __popc(lmask);
                unsigned F = (~A0) & 0xffffu;
                if ((lane < MSLOT) && ((refresh >> lane) & 1u)) t_cnt = 5;
                bool doins = false; int srcl = 0;
                if ((lane < MSLOT) && ((F >> lane) & 1u)) {
                    int q = __popc(F & ((1u << lane) - 1u));
                    if (q < nL) { doins = true; srcl = (int)__fns(lmask, 0, q + 1); }
                }
                int   nti = __shfl_sync(FULLM, pci,  srcl);
                int   ntj = __shfl_sync(FULLM, pcj,  srcl);
                float nmr = __shfl_sync(FULLM, pmre, srcl);
                float nmi = __shfl_sync(FULLM, pmim, srcl);
                if (doins) { t_ti = nti; t_tj = ntj; t_mre = nmr; t_mim = nmi; t_cnt = 5; }
            }

            // ---- decay + liveness ----
            bool alive = false;
            if (lane < MSLOT) {
                t_mre *= 0.9f; t_mim *= 0.9f; t_cnt -= 1;
                alive = (t_cnt > 0) && (sqrtf(t_mre * t_mre + t_mim * t_mim) > 1e-6f);
                if (!alive) { t_cnt = 0; t_mre = 0.f; t_mim = 0.f; }
            }
            // endpoint mapping: lane l -> (slot l, ti), lane l+16 -> (slot l-16, tj)
            unsigned am = __ballot_sync(FULLM, alive);        // bits 0..15
            int slot = lane & 15;
            bool myact = ((am >> slot) & 1u) != 0u;
            int   tis = __shfl_sync(FULLM, t_ti,  slot);
            int   tjs = __shfl_sync(FULLM, t_tj,  slot);
            float mr  = __shfl_sync(FULLM, t_mre, slot);
            float mi  = __shfl_sync(FULLM, t_mim, slot);
            int eidx = (lane < 16) ? tis : tjs;
            if (myact) {
                atomicAdd(&d_re[eidx], 0.1f * mr);
                atomicAdd(&d_im[eidx], 0.1f * mi);
            }
            __syncwarp();
            // ---- sparse corrections: one leader per unique affected index ----
            float dnorm = 0.f;
            unsigned actm = am | (am << 16);
            if (myact) {
                unsigned peers = __match_any_sync(actm, eidx);
                if ((int)(__ffs(peers) - 1) == lane) {
                    float dre = d_re[eidx], dim = d_im[eidx];
                    float sr = s_re[eidx], si = s_im[eidx];
                    float h  = hb[eidx];
                    float tr = tbres[eidx], tii = tbims[eidx];
                    float a0, c0, a1, c1;
                    upd_elem(sr, si, 0.f, 0.f, h, tr, tii, eta, a0, c0);
                    upd_elem(sr, si, dre, dim, h, tr, tii, eta, a1, c1);
                    dnorm = (a1 * a1 + c1 * c1) - (a0 * a0 + c0 * c0);
                    d_re[eidx] = a1; d_im[eidx] = c1;   // corrected, unnormalized
                    atomicOr(&bmap[eidx >> 5], 1u << (eidx & 31));
                }
            }
#pragma unroll
            for (int off = 16; off; off >>= 1)
                dnorm += __shfl_xor_sync(FULLM, dnorm, off);
            if (lane == 0) red[NWD] = dnorm;

            __syncthreads();   // (C) — serial warp's arrival
            // serial warp skips P4; next barrier it meets is (A) of step t+1
        }
        // next step: data warps' P4 SMEM writes vs serial reads are ordered by
        // barrier (A); cand buffers of t+1 are written after (A) while serial
        // finished reading them before (C).
    }
}

extern "C" void kernel_launch(void* const* d_in, const int* in_sizes, int n_in,
                              void* d_out, int out_size) {
    const float* x       = (const float*)d_in[0];
    const float* tape_re = (const float*)d_in[1];
    const float* tape_im = (const float*)d_in[2];
    const float* eta_p   = (const float*)d_in[3];
    const float* tb_re   = (const float*)d_in[4];
    const float* tb_im   = (const float*)d_in[5];
    float* out = (float*)d_out;

    static int attr_done = 0;
    if (!attr_done) {
        cudaFuncSetAttribute(me_bind_kernel,
                             cudaFuncAttributeMaxDynamicSharedMemorySize, SMEM_BYTES);
        attr_done = 1;
    }
    int B = in_sizes[0] / (TSTEPS * DIMN);   // 64
    me_bind_kernel<<<B, NTOT, SMEM_BYTES>>>(x, tape_re, tape_im, eta_p, tb_re, tb_im, out);
}